// round 9
// baseline (speedup 1.0000x reference)
#include <cuda_runtime.h>

typedef unsigned long long ull;

#define T_LEN 8192
#define NLAG  64

// layout: phys(u) = u + 6*(u>>6)  (pad 6 words per 64-elem chunk)
//  - per-thread chunk = 64 elems -> lane stride 70 words; 70 mod 32 = 6,
//    6*l distinct mod 32 over each 16-lane phase -> conflict-free LDS.64
//  - even skew -> logical-even pairs stay 8B-aligned
//  - block-crossing bump is lane-invariant (chunks are 64-aligned)
#define PHYS_N 9024            // phys(8255)=9023, +1
#define SKP(u) ((u) + 6 * ((u) >> 6))
#define DSMEM_BYTES (2 * PHYS_N * 4)   // 72192 B -> 3 CTAs/SM fit (217 KB)

__device__ __forceinline__ ull lds64(const float* p) {
    return *reinterpret_cast<const ull*>(p);
}
__device__ __forceinline__ void fma2(ull& d, ull a, ull b) {
    asm("fma.rn.f32x2 %0, %1, %2, %0;" : "+l"(d) : "l"(a), "l"(b));
}
__device__ __forceinline__ float pksum(ull v) {   // epilogue only
    float lo, hi;
    asm("mov.b64 {%0, %1}, %2;" : "=f"(lo), "=f"(hi) : "l"(v));
    return lo + hi;
}

// Lag-group K0..K0+15 (K0 = 1+16g, odd). Dual-parity pairing:
//   acc[2e]   : lag K0+2e   (odd)  -> copy2 pair at logical 2j+K0-1
//   acc[2e+1] : lag K0+2e+1 (even) -> copy1 pair at logical 2j+K0+1
// TM = 64 time points / thread / segment, 2 segments. All operands are
// direct aligned LDS.64 — zero packs/unpacks. 1-step prefetch on W and A.
template<int K0>
__device__ __forceinline__ void corr_group(const float* __restrict__ sm1,
                                           const float* __restrict__ sm2,
                                           int tt, ull* __restrict__ acc)
{
#pragma unroll 1
    for (int seg = 0; seg < 2; ++seg) {
        // chunk = seg*64 + tt ; base phys = 70*chunk
        const float* p1 = sm1 + seg * 4480 + tt * 70;
        const float* p2 = sm2 + seg * 4480 + tt * 70;

        ull W1[40], W2[40], A[32];
#pragma unroll
        for (int j = 0; j < 8; ++j) {
            W1[j] = lds64(p1 + SKP(2 * j + K0 + 1));
            W2[j] = lds64(p2 + SKP(2 * j + K0 - 1));
        }
        A[0] = lds64(p1);

#pragma unroll
        for (int m = 0; m < 32; ++m) {
            // slide: prefetch next-step operands (1 step ~= 32 cyc lead)
            if (m < 31) {
                A[m + 1]  = lds64(p1 + SKP(2 * (m + 1)));
                W1[m + 8] = lds64(p1 + SKP(2 * (m + 8) + K0 + 1));
                W2[m + 8] = lds64(p2 + SKP(2 * (m + 8) + K0 - 1));
            }
#pragma unroll
            for (int e = 0; e < 8; ++e) {
                fma2(acc[2 * e],     A[m], W2[m + e]);   // odd  lag K0+2e
                fma2(acc[2 * e + 1], A[m], W1[m + e]);   // even lag K0+2e+1
            }
        }
    }
}

__global__ __launch_bounds__(256, 3)
void autocorr_kernel(const float* __restrict__ X, float* __restrict__ out)
{
    extern __shared__ __align__(16) float dsm[];
    float* sm1 = dsm;             // copy1: xc[i]
    float* sm2 = dsm + PHYS_N;    // copy2: xc[i+1]

    __shared__ float red[8][16];
    __shared__ float wsum[8], wsq[8];
    __shared__ float stats[2];    // [0]=mean, [1]=1/var0

    const int tid = threadIdx.x;
    const int b   = blockIdx.x;
    const float4* Xr = reinterpret_cast<const float4*>(X + (size_t)b * T_LEN);

    // ---------------- Phase 1: load, mean & sumsq, centered dual stores
    float4 xv[8];
    float s = 0.f, q = 0.f;
#pragma unroll
    for (int r = 0; r < 8; ++r) {
        xv[r] = Xr[tid + r * 256];
        s += xv[r].x + xv[r].y + xv[r].z + xv[r].w;
        q += xv[r].x * xv[r].x + xv[r].y * xv[r].y
           + xv[r].z * xv[r].z + xv[r].w * xv[r].w;
    }
#pragma unroll
    for (int o = 16; o > 0; o >>= 1) {
        s += __shfl_xor_sync(0xffffffffu, s, o);
        q += __shfl_xor_sync(0xffffffffu, q, o);
    }
    if ((tid & 31) == 0) { wsum[tid >> 5] = s; wsq[tid >> 5] = q; }
    __syncthreads();
    if (tid == 0) {
        float S = 0.f, Q = 0.f;
#pragma unroll
        for (int i = 0; i < 8; ++i) { S += wsum[i]; Q += wsq[i]; }
        float mean = S * (1.f / (float)T_LEN);
        stats[0] = mean;
        stats[1] = 1.f / (Q - (float)T_LEN * mean * mean);  // 1/T cancels in ratio
    }
    __syncthreads();
    const float mean = stats[0];

#pragma unroll
    for (int r = 0; r < 8; ++r) {
        const int i0 = (tid + r * 256) * 4;
        const float v0 = xv[r].x - mean, v1 = xv[r].y - mean;
        const float v2 = xv[r].z - mean, v3 = xv[r].w - mean;
        // copy1: i0..i0+3 share one 64-block (i0 mod 64 <= 60) -> one skew
        const int p = SKP(i0);
        *reinterpret_cast<float2*>(&sm1[p])     = make_float2(v0, v1);
        *reinterpret_cast<float2*>(&sm1[p + 2]) = make_float2(v2, v3);
        // copy2: value of logical t -> slot t-1 (scalar, per-slot skew)
        if (i0 > 0) { const int j = i0 - 1; sm2[SKP(j)] = v0; }
        { const int j = i0;     sm2[SKP(j)] = v1; }
        { const int j = i0 + 1; sm2[SKP(j)] = v2; }
        { const int j = i0 + 2; sm2[SKP(j)] = v3; }
    }
    if (tid < NLAG) {   // zero pads: x[8192..8255] = 0 in both copies
        const int i1 = T_LEN + tid;
        sm1[SKP(i1)] = 0.f;
        const int i2 = T_LEN - 1 + tid;
        sm2[SKP(i2)] = 0.f;
    }
    __syncthreads();

    // ---------------- Phase 2: lag-group correlation (pure LDS.64 + FMA2)
    const int g  = tid >> 6;
    const int tt = tid & 63;

    ull acc[16];
#pragma unroll
    for (int i = 0; i < 16; ++i) acc[i] = 0ull;

    switch (g) {
        case 0: corr_group<1 >(sm1, sm2, tt, acc); break;
        case 1: corr_group<17>(sm1, sm2, tt, acc); break;
        case 2: corr_group<33>(sm1, sm2, tt, acc); break;
        default: corr_group<49>(sm1, sm2, tt, acc); break;
    }

    // ---------------- Phase 3: reduce, normalize, store
    float v[16];
#pragma unroll
    for (int i = 0; i < 16; ++i) v[i] = pksum(acc[i]);
#pragma unroll
    for (int o = 16; o > 0; o >>= 1) {
#pragma unroll
        for (int i = 0; i < 16; ++i)
            v[i] += __shfl_xor_sync(0xffffffffu, v[i], o);
    }
    if ((tid & 31) == 0) {
        int wid = tid >> 5;
#pragma unroll
        for (int i = 0; i < 16; ++i) red[wid][i] = v[i];
    }
    __syncthreads();
    if (tid < 64) {
        int gg = tid >> 4, dk = tid & 15;   // lag = 16*gg + dk + 1 -> out col = tid
        float sum = red[2 * gg][dk] + red[2 * gg + 1][dk];
        out[(size_t)b * NLAG + tid] = sum * stats[1];
    }
}

extern "C" void kernel_launch(void* const* d_in, const int* in_sizes, int n_in,
                              void* d_out, int out_size)
{
    const float* X = (const float*)d_in[0];
    float* out = (float*)d_out;
    const int B = in_sizes[0] / T_LEN;   // 4096

    static int attr_done = 0;            // idempotent attribute set (not a work guard)
    if (!attr_done) {
        cudaFuncSetAttribute(autocorr_kernel,
                             cudaFuncAttributeMaxDynamicSharedMemorySize,
                             DSMEM_BYTES);
        attr_done = 1;
    }
    autocorr_kernel<<<B, 256, DSMEM_BYTES>>>(X, out);
}

// round 11
// speedup vs baseline: 2.2678x; 2.2678x over previous
#include <cuda_runtime.h>
#include <cstdint>

#define T_LEN 8192
#define NLAG  64

// x buffer: 64 chunks of 128 values, stride 136 (pad 8) + 64-word zero chunk.
// stride 136 mod 32 = 8 -> fragment gathers (addr = 136*(lane%4) + (lane>>2))
// touch 8*(lane%4)+(lane>>2): all 32 banks distinct -> conflict-free.
#define XSTR   136
#define XWORDS (XSTR * 64 + 64)          // 8768 floats
// band buffer: 8 m-tiles x 16 rows x 80 cols fp32 = 10240 floats (aliases xbuf)
#define BANDW  10240
#define DSMEM_BYTES (BANDW * 4)          // 40960 >= XWORDS*4 (35072)

__device__ __forceinline__ uint32_t tf32r(float x) {
    uint32_t r;
    asm("cvt.rna.tf32.f32 %0, %1;" : "=r"(r) : "f"(x));
    return r;
}
__device__ __forceinline__ void mma_tf32(float* c, const uint32_t* a,
                                         uint32_t b0, uint32_t b1) {
    asm volatile(
        "mma.sync.aligned.m16n8k8.row.col.f32.tf32.tf32.f32 "
        "{%0,%1,%2,%3}, {%4,%5,%6,%7}, {%8,%9}, {%0,%1,%2,%3};"
        : "+f"(c[0]), "+f"(c[1]), "+f"(c[2]), "+f"(c[3])
        : "r"(a[0]), "r"(a[1]), "r"(a[2]), "r"(a[3]), "r"(b0), "r"(b1));
}

__global__ __launch_bounds__(256, 3)
void autocorr_mma_kernel(const float* __restrict__ X, float* __restrict__ out)
{
    extern __shared__ __align__(16) float dsm[];
    float* xb = dsm;                       // tf32-rounded centered row
    float* band = dsm;                     // aliased AFTER mma loop completes
    const uint32_t* xu = reinterpret_cast<const uint32_t*>(dsm);

    __shared__ float wsum[8], wsq[8];
    __shared__ float stats[2];             // [0]=mean, [1]=1/var0

    const int tid = threadIdx.x;
    const int wid = tid >> 5;              // m-tile index (rows 16*wid..+15)
    const int lid = tid & 31;
    const int r4  = lid >> 2;              // fragment row / n within tile
    const int c4  = lid & 3;               // fragment k index
    const int b   = blockIdx.x;

    const float4* Xr = reinterpret_cast<const float4*>(X + (size_t)b * T_LEN);

    // ---------------- Phase 1: load row, mean & sumsq (exact fp32) ----------
    float4 xv[8];
    float s = 0.f, q = 0.f;
#pragma unroll
    for (int r = 0; r < 8; ++r) {
        xv[r] = Xr[tid + r * 256];
        s += xv[r].x + xv[r].y + xv[r].z + xv[r].w;
        q += xv[r].x * xv[r].x + xv[r].y * xv[r].y
           + xv[r].z * xv[r].z + xv[r].w * xv[r].w;
    }
#pragma unroll
    for (int o = 16; o > 0; o >>= 1) {
        s += __shfl_xor_sync(0xffffffffu, s, o);
        q += __shfl_xor_sync(0xffffffffu, q, o);
    }
    if (lid == 0) { wsum[wid] = s; wsq[wid] = q; }
    __syncthreads();
    if (tid == 0) {
        float S = 0.f, Q = 0.f;
#pragma unroll
        for (int i = 0; i < 8; ++i) { S += wsum[i]; Q += wsq[i]; }
        float mean = S * (1.f / (float)T_LEN);
        stats[0] = mean;
        stats[1] = 1.f / (Q - (float)T_LEN * mean * mean);  // 1/T cancels in ratio
    }
    __syncthreads();
    const float mean = stats[0];

    // ---------------- Phase 2: centered tf32 values -> padded xbuf ----------
#pragma unroll
    for (int r = 0; r < 8; ++r) {
        const int t0 = (tid + r * 256) * 4;
        const int ad = XSTR * (t0 >> 7) + (t0 & 127);   // 4 elems same chunk
        uint4 c;
        c.x = tf32r(xv[r].x - mean);
        c.y = tf32r(xv[r].y - mean);
        c.z = tf32r(xv[r].z - mean);
        c.w = tf32r(xv[r].w - mean);
        *reinterpret_cast<uint4*>(&xb[ad]) = c;
    }
    if (tid < NLAG) xb[XSTR * 64 + tid] = 0.f;          // zero chunk (t >= T)
    __syncthreads();

    // ---------------- Phase 3: band GEMM via mma.sync (tensor pipe) ---------
    // C[t][*]: n-tile t covers cols u0 = 16*wid + 8*t, band cols [0,80) local.
    float C[10][4];
#pragma unroll
    for (int t = 0; t < 10; ++t)
#pragma unroll
        for (int j = 0; j < 4; ++j) C[t][j] = 0.f;

    const int aoff = 16 * wid + r4;
#pragma unroll 2
    for (int ks = 0; ks < 8; ++ks) {
        const int i0 = 8 * ks;
        const int rowA = XSTR * (i0 + c4);
        const int rowB = XSTR * (i0 + c4 + 4);
        uint32_t a[4];
        a[0] = xu[rowA + aoff];
        a[1] = xu[rowA + aoff + 8];
        a[2] = xu[rowB + aoff];
        a[3] = xu[rowB + aoff + 8];
#pragma unroll
        for (int t = 0; t < 10; ++t) {
            const int u0 = 16 * wid + 8 * t;
            const int ub = u0 + ((u0 >= 128) ? 8 : 0) + r4;  // chunk-crossing bump
            const uint32_t b0 = xu[rowA + ub];
            const uint32_t b1 = xu[rowB + ub];
            mma_tf32(C[t], a, b0, b1);
        }
    }
    __syncthreads();   // all warps done reading xbuf; band may now alias it

    // ---------------- Phase 4: C fragments -> band smem ---------------------
    // c0,c1 -> (row=r4,    cols 8t+2c4, +1); c2,c3 -> (row=r4+8, same cols)
    {
        float* bp = band + wid * 1280;
#pragma unroll
        for (int t = 0; t < 10; ++t) {
            const int cb = 8 * t + 2 * c4;
            *reinterpret_cast<float2*>(&bp[r4 * 80 + cb])       = make_float2(C[t][0], C[t][1]);
            *reinterpret_cast<float2*>(&bp[(r4 + 8) * 80 + cb]) = make_float2(C[t][2], C[t][3]);
        }
    }
    __syncthreads();

    // ---------------- Phase 5: diagonal reduce + normalize + store ----------
    if (tid < NLAG) {
        const int k = tid + 1;
        float acc = 0.f;
#pragma unroll
        for (int m = 0; m < 8; ++m) {
            const float* bp = band + m * 1280;
            float ps = 0.f;
#pragma unroll
            for (int r = 0; r < 16; ++r)
                ps += bp[r * 80 + r + k];   // col_local - row = lag
            acc += ps;
        }
        out[(size_t)b * NLAG + tid] = acc * stats[1];
    }
}

extern "C" void kernel_launch(void* const* d_in, const int* in_sizes, int n_in,
                              void* d_out, int out_size)
{
    const float* X = (const float*)d_in[0];
    float* out = (float*)d_out;
    const int B = in_sizes[0] / T_LEN;   // 4096

    autocorr_mma_kernel<<<B, 256, DSMEM_BYTES>>>(X, out);
}